// round 1
// baseline (speedup 1.0000x reference)
#include <cuda_runtime.h>
#include <math.h>

#define DIMN     2048
#define NHEADS   16
#define HEAD_DIM 128
#define BATCH    2
#define SEQ      2048
#define MTOT     (BATCH*SEQ)   /* 4096 */

// ---------------- scratch (device globals; no runtime alloc allowed) --------
__device__ float g_q[(size_t)MTOT*DIMN];
__device__ float g_k[(size_t)MTOT*DIMN];
__device__ float g_v[(size_t)MTOT*DIMN];
__device__ float g_o[(size_t)MTOT*DIMN];

// ---------------- GEMM: C[m,n] = sum_k A[m,k] * W[n,k]  (both row-major) ----
#define BM 128
#define BN 128
#define BK 16

__global__ __launch_bounds__(256)
void gemm_nt(const float* __restrict__ A, const float* __restrict__ W,
             float* __restrict__ C, int Mdim, int Ndim, int Kdim)
{
    __shared__ float As[BK][BM + 4];
    __shared__ float Bs[BK][BN + 4];

    const int tid = threadIdx.x;
    const int tx  = tid & 15;
    const int ty  = tid >> 4;
    const int m0  = blockIdx.y * BM;
    const int n0  = blockIdx.x * BN;

    float acc[8][8];
    #pragma unroll
    for (int i = 0; i < 8; i++)
        #pragma unroll
        for (int j = 0; j < 8; j++)
            acc[i][j] = 0.f;

    for (int k0 = 0; k0 < Kdim; k0 += BK) {
        // load 128x16 tiles of A and W, transposed into k-major smem
        #pragma unroll
        for (int l = 0; l < 2; l++) {
            int idx = tid + l * 256;       // 0..511
            int row = idx >> 2;            // 0..127
            int kg  = idx & 3;             // 0..3  (group of 4 k)
            float4 va = *(const float4*)&A[(size_t)(m0 + row) * Kdim + k0 + kg * 4];
            As[kg*4+0][row] = va.x;  As[kg*4+1][row] = va.y;
            As[kg*4+2][row] = va.z;  As[kg*4+3][row] = va.w;
            float4 vb = *(const float4*)&W[(size_t)(n0 + row) * Kdim + k0 + kg * 4];
            Bs[kg*4+0][row] = vb.x;  Bs[kg*4+1][row] = vb.y;
            Bs[kg*4+2][row] = vb.z;  Bs[kg*4+3][row] = vb.w;
        }
        __syncthreads();

        #pragma unroll
        for (int kk = 0; kk < BK; kk++) {
            float a[8], b[8];
            *(float4*)&a[0] = *(const float4*)&As[kk][ty * 4];
            *(float4*)&a[4] = *(const float4*)&As[kk][64 + ty * 4];
            *(float4*)&b[0] = *(const float4*)&Bs[kk][tx * 4];
            *(float4*)&b[4] = *(const float4*)&Bs[kk][64 + tx * 4];
            #pragma unroll
            for (int i = 0; i < 8; i++)
                #pragma unroll
                for (int j = 0; j < 8; j++)
                    acc[i][j] += a[i] * b[j];
        }
        __syncthreads();
    }

    #pragma unroll
    for (int i = 0; i < 8; i++) {
        int r = m0 + ((i < 4) ? (ty * 4 + i) : (64 + ty * 4 + (i - 4)));
        float4 v0 = make_float4(acc[i][0], acc[i][1], acc[i][2], acc[i][3]);
        float4 v1 = make_float4(acc[i][4], acc[i][5], acc[i][6], acc[i][7]);
        *(float4*)&C[(size_t)r * Ndim + n0 + tx * 4]      = v0;
        *(float4*)&C[(size_t)r * Ndim + n0 + 64 + tx * 4] = v1;
    }
}

// ---------------- RoPE on q and k (in place) --------------------------------
__global__ void rope_kernel(float* __restrict__ q, float* __restrict__ k,
                            const float* __restrict__ fc, const float* __restrict__ fs)
{
    int idx = blockIdx.x * blockDim.x + threadIdx.x;      // pair index
    const int PAIRS_PER_ROW = DIMN / 2;                   // 1024
    if (idx >= MTOT * PAIRS_PER_ROW) return;
    int row = idx / PAIRS_PER_ROW;                        // 0..4095 (b-major)
    int p   = idx % PAIRS_PER_ROW;                        // 0..1023
    int s   = row & (SEQ - 1);                            // row % SEQ
    int i   = p & (HEAD_DIM / 2 - 1);                     // p % 64
    float c  = fc[s * (HEAD_DIM / 2) + i];
    float sn = fs[s * (HEAD_DIM / 2) + i];
    size_t base = (size_t)row * DIMN + p * 2;
    float qr = q[base], qi = q[base + 1];
    q[base]     = qr * c - qi * sn;
    q[base + 1] = qr * sn + qi * c;
    float kr = k[base], ki = k[base + 1];
    k[base]     = kr * c - ki * sn;
    k[base + 1] = kr * sn + ki * c;
}

// ---------------- Flash attention (fp32, online softmax) --------------------
#define BQ  64
#define BKV 64
#define QT_STRIDE 68        /* [128][68] transposed q tile */
#define KT_STRIDE 68        /* [128][68] transposed k tile */
#define VS_STRIDE 132       /* [64][132] natural v tile    */
#define PS_STRIDE 68        /* [64][68]  probability tile  */

#define SMEM_FLOATS (128*QT_STRIDE + 128*KT_STRIDE + BKV*VS_STRIDE + BQ*PS_STRIDE)

__global__ __launch_bounds__(256)
void attn_kernel(const float* __restrict__ Q, const float* __restrict__ K,
                 const float* __restrict__ V, const float* __restrict__ mask,
                 float* __restrict__ O)
{
    extern __shared__ float sm[];
    float* Qt = sm;                              // [128][68]  d-major
    float* Kt = Qt + 128 * QT_STRIDE;            // [128][68]  d-major
    float* Vs = Kt + 128 * KT_STRIDE;            // [64][132]  kv-row major
    float* Ps = Vs + BKV * VS_STRIDE;            // [64][68]

    const int tid = threadIdx.x;
    const int tx  = tid & 15;
    const int ty  = tid >> 4;
    const int q0  = blockIdx.x * BQ;
    const int h   = blockIdx.y;
    const int b   = blockIdx.z;
    const float scale = 0.08838834764831845f;    // 1/sqrt(128)

    // load Q tile, transposed + pre-scaled
    #pragma unroll
    for (int l = 0; l < 8; l++) {
        int idx = tid + l * 256;                 // 0..2047
        int r   = idx >> 5;                      // 0..63
        int d4  = idx & 31;                      // 0..31
        float4 v = *(const float4*)&Q[((size_t)(b * SEQ + q0 + r)) * DIMN + h * HEAD_DIM + d4 * 4];
        Qt[(d4*4+0) * QT_STRIDE + r] = v.x * scale;
        Qt[(d4*4+1) * QT_STRIDE + r] = v.y * scale;
        Qt[(d4*4+2) * QT_STRIDE + r] = v.z * scale;
        Qt[(d4*4+3) * QT_STRIDE + r] = v.w * scale;
    }

    float acc[4][8];
    float m_i[4], l_i[4];
    #pragma unroll
    for (int i = 0; i < 4; i++) {
        m_i[i] = -1e30f; l_i[i] = 0.f;
        #pragma unroll
        for (int j = 0; j < 8; j++) acc[i][j] = 0.f;
    }

    for (int kv0 = 0; kv0 < SEQ; kv0 += BKV) {
        __syncthreads();   // previous PV done; Qt stores done (first iter)
        // load K (transposed) and V (natural)
        #pragma unroll
        for (int l = 0; l < 8; l++) {
            int idx = tid + l * 256;
            int r   = idx >> 5;
            int d4  = idx & 31;
            size_t goff = ((size_t)(b * SEQ + kv0 + r)) * DIMN + h * HEAD_DIM + d4 * 4;
            float4 kv = *(const float4*)&K[goff];
            Kt[(d4*4+0) * KT_STRIDE + r] = kv.x;
            Kt[(d4*4+1) * KT_STRIDE + r] = kv.y;
            Kt[(d4*4+2) * KT_STRIDE + r] = kv.z;
            Kt[(d4*4+3) * KT_STRIDE + r] = kv.w;
            float4 vv = *(const float4*)&V[goff];
            *(float4*)&Vs[r * VS_STRIDE + d4 * 4] = vv;
        }
        __syncthreads();

        // S tile: rows ty*4+i (q), cols tx*4+j (k)
        float s[4][4];
        #pragma unroll
        for (int i = 0; i < 4; i++)
            #pragma unroll
            for (int j = 0; j < 4; j++) s[i][j] = 0.f;

        #pragma unroll 4
        for (int kk = 0; kk < HEAD_DIM; kk++) {
            float a[4], bb[4];
            *(float4*)a  = *(const float4*)&Qt[kk * QT_STRIDE + ty * 4];
            *(float4*)bb = *(const float4*)&Kt[kk * KT_STRIDE + tx * 4];
            #pragma unroll
            for (int i = 0; i < 4; i++)
                #pragma unroll
                for (int j = 0; j < 4; j++)
                    s[i][j] += a[i] * bb[j];
        }

        // + mask
        #pragma unroll
        for (int i = 0; i < 4; i++) {
            const float* mrow = &mask[(size_t)(q0 + ty * 4 + i) * SEQ + kv0 + tx * 4];
            #pragma unroll
            for (int j = 0; j < 4; j++) s[i][j] += mrow[j];
        }

        // online softmax (reduce across the 16 tx lanes of this warp half)
        #pragma unroll
        for (int i = 0; i < 4; i++) {
            float mx = fmaxf(fmaxf(s[i][0], s[i][1]), fmaxf(s[i][2], s[i][3]));
            #pragma unroll
            for (int o = 1; o < 16; o <<= 1)
                mx = fmaxf(mx, __shfl_xor_sync(0xffffffffu, mx, o));
            float mnew  = fmaxf(m_i[i], mx);
            float alpha = __expf(m_i[i] - mnew);
            float p[4];
            float rs = 0.f;
            #pragma unroll
            for (int j = 0; j < 4; j++) { p[j] = __expf(s[i][j] - mnew); rs += p[j]; }
            #pragma unroll
            for (int o = 1; o < 16; o <<= 1)
                rs += __shfl_xor_sync(0xffffffffu, rs, o);
            l_i[i] = l_i[i] * alpha + rs;
            m_i[i] = mnew;
            #pragma unroll
            for (int j = 0; j < 8; j++) acc[i][j] *= alpha;
            *(float4*)&Ps[(ty * 4 + i) * PS_STRIDE + tx * 4] = make_float4(p[0], p[1], p[2], p[3]);
        }
        __syncthreads();

        // O += P @ V : cols tx*4+j and 64+tx*4+j
        #pragma unroll 8
        for (int kk = 0; kk < BKV; kk++) {
            float pv[4];
            #pragma unroll
            for (int i = 0; i < 4; i++) pv[i] = Ps[(ty * 4 + i) * PS_STRIDE + kk];
            float vr[8];
            *(float4*)&vr[0] = *(const float4*)&Vs[kk * VS_STRIDE + tx * 4];
            *(float4*)&vr[4] = *(const float4*)&Vs[kk * VS_STRIDE + 64 + tx * 4];
            #pragma unroll
            for (int i = 0; i < 4; i++)
                #pragma unroll
                for (int j = 0; j < 8; j++)
                    acc[i][j] += pv[i] * vr[j];
        }
    }

    // normalize + store
    #pragma unroll
    for (int i = 0; i < 4; i++) {
        float inv = 1.f / l_i[i];
        size_t orow = ((size_t)(b * SEQ + q0 + ty * 4 + i)) * DIMN + h * HEAD_DIM;
        float4 o0 = make_float4(acc[i][0]*inv, acc[i][1]*inv, acc[i][2]*inv, acc[i][3]*inv);
        float4 o1 = make_float4(acc[i][4]*inv, acc[i][5]*inv, acc[i][6]*inv, acc[i][7]*inv);
        *(float4*)&O[orow + tx * 4]      = o0;
        *(float4*)&O[orow + 64 + tx * 4] = o1;
    }
}

// ---------------- launcher ---------------------------------------------------
extern "C" void kernel_launch(void* const* d_in, const int* in_sizes, int n_in,
                              void* d_out, int out_size)
{
    const float* x    = (const float*)d_in[0];
    const float* fcos = (const float*)d_in[1];
    const float* fsin = (const float*)d_in[2];
    const float* mask = (const float*)d_in[3];
    const float* wq   = (const float*)d_in[4];
    const float* wk   = (const float*)d_in[5];
    const float* wv   = (const float*)d_in[6];
    const float* wo   = (const float*)d_in[7];
    float* out = (float*)d_out;

    float *q, *k, *v, *o;
    cudaGetSymbolAddress((void**)&q, g_q);
    cudaGetSymbolAddress((void**)&k, g_k);
    cudaGetSymbolAddress((void**)&v, g_v);
    cudaGetSymbolAddress((void**)&o, g_o);

    const int attn_smem = SMEM_FLOATS * (int)sizeof(float);
    cudaFuncSetAttribute(attn_kernel, cudaFuncAttributeMaxDynamicSharedMemorySize, attn_smem);

    dim3 gemm_grid(DIMN / BN, MTOT / BM);   // (16, 32)
    dim3 gemm_block(256);

    // 1. projections
    gemm_nt<<<gemm_grid, gemm_block>>>(x, wq, q, MTOT, DIMN, DIMN);
    gemm_nt<<<gemm_grid, gemm_block>>>(x, wk, k, MTOT, DIMN, DIMN);
    gemm_nt<<<gemm_grid, gemm_block>>>(x, wv, v, MTOT, DIMN, DIMN);

    // 2. RoPE on q, k
    {
        int total = MTOT * (DIMN / 2);
        rope_kernel<<<(total + 255) / 256, 256>>>(q, k, fcos, fsin);
    }

    // 3. attention
    {
        dim3 grid(SEQ / BQ, NHEADS, BATCH);   // (32, 16, 2)
        attn_kernel<<<grid, 256, attn_smem>>>(q, k, v, mask, o);
    }

    // 4. output projection -> d_out
    gemm_nt<<<gemm_grid, gemm_block>>>(o, wo, out, MTOT, DIMN, DIMN);
}

// round 2
// speedup vs baseline: 1.6390x; 1.6390x over previous
#include <cuda_runtime.h>
#include <math.h>

#define DIMN     2048
#define NHEADS   16
#define HEAD_DIM 128
#define BATCH    2
#define SEQ      2048
#define MTOT     (BATCH*SEQ)   /* 4096 */

// ---------------- scratch (device globals; no runtime alloc allowed) --------
__device__ float g_q [(size_t)MTOT*DIMN];
__device__ float g_k [(size_t)MTOT*DIMN];
__device__ float g_v [(size_t)MTOT*DIMN];
__device__ float g_o [(size_t)MTOT*DIMN];
__device__ float g_xr[(size_t)MTOT*DIMN];          // tf32-rounded input
__device__ float g_wq[(size_t)DIMN*DIMN];
__device__ float g_wk[(size_t)DIMN*DIMN];
__device__ float g_wv[(size_t)DIMN*DIMN];
__device__ float g_wo[(size_t)DIMN*DIMN];

// ---------------- tf32 rounding pass (rna, unbiased) -------------------------
__global__ void round_tf32_kernel(const float* __restrict__ in,
                                  float* __restrict__ out, int n4)
{
    int i = blockIdx.x * blockDim.x + threadIdx.x;
    if (i >= n4) return;
    float4 v = ((const float4*)in)[i];
    unsigned a, b, c, d;
    asm("cvt.rna.tf32.f32 %0, %1;" : "=r"(a) : "f"(v.x));
    asm("cvt.rna.tf32.f32 %0, %1;" : "=r"(b) : "f"(v.y));
    asm("cvt.rna.tf32.f32 %0, %1;" : "=r"(c) : "f"(v.z));
    asm("cvt.rna.tf32.f32 %0, %1;" : "=r"(d) : "f"(v.w));
    float4 o;
    o.x = __uint_as_float(a); o.y = __uint_as_float(b);
    o.z = __uint_as_float(c); o.w = __uint_as_float(d);
    ((float4*)out)[i] = o;
}

// ---------------- tf32 tensor-core GEMM: C[m,n] = sum_k A[m,k]*W[n,k] --------
// inputs pre-rounded to tf32 (low mantissa bits zero) -> no cvt in hot loop
#define TBM 128
#define TBN 128
#define TBK 32
#define ASTR 36          /* floats per smem row: 32 + 4 pad, 144B (16B-mult) */

#define CP_ASYNC16(dst, src) \
    asm volatile("cp.async.cg.shared.global [%0], [%1], 16;\n" :: "r"(dst), "l"(src))

__device__ __forceinline__ void gemm_load_stage(
    float* as, float* bs, const float* __restrict__ A, const float* __restrict__ W,
    int m0, int n0, int k0, int Kdim, int tid)
{
    #pragma unroll
    for (int i = 0; i < 4; i++) {
        int idx = tid + i * 256;          // 0..1023
        int row = idx >> 3;               // 0..127
        int c4  = (idx & 7) * 4;          // 0..28
        unsigned da = (unsigned)__cvta_generic_to_shared(as + row * ASTR + c4);
        CP_ASYNC16(da, A + (size_t)(m0 + row) * Kdim + k0 + c4);
        unsigned db = (unsigned)__cvta_generic_to_shared(bs + row * ASTR + c4);
        CP_ASYNC16(db, W + (size_t)(n0 + row) * Kdim + k0 + c4);
    }
    asm volatile("cp.async.commit_group;\n" ::);
}

extern __shared__ float smem_gemm[];

__global__ __launch_bounds__(256, 2)
void gemm_tf32(const float* __restrict__ A, const float* __restrict__ W,
               float* __restrict__ C, int Mdim, int Ndim, int Kdim)
{
    float* As = smem_gemm;                     // [2][128][ASTR]
    float* Bs = smem_gemm + 2 * 128 * ASTR;    // [2][128][ASTR]

    const int tid  = threadIdx.x;
    const int wid  = tid >> 5;
    const int lane = tid & 31;
    const int lr   = lane >> 2;                // 0..7
    const int lc   = lane & 3;                 // 0..3
    const int wm   = (wid & 1) * 64;           // warp tile 64m x 32n
    const int wn   = (wid >> 1) * 32;
    const int m0   = blockIdx.y * TBM;
    const int n0   = blockIdx.x * TBN;

    float acc[4][4][4];
    #pragma unroll
    for (int mi = 0; mi < 4; mi++)
        #pragma unroll
        for (int nj = 0; nj < 4; nj++)
            #pragma unroll
            for (int c = 0; c < 4; c++) acc[mi][nj][c] = 0.f;

    const int NK = Kdim / TBK;                 // 64

    gemm_load_stage(As, Bs, A, W, m0, n0, 0, Kdim, tid);

    for (int kt = 0; kt < NK; kt++) {
        int cur = kt & 1;
        if (kt + 1 < NK) {
            gemm_load_stage(As + ((kt + 1) & 1) * 128 * ASTR,
                            Bs + ((kt + 1) & 1) * 128 * ASTR,
                            A, W, m0, n0, (kt + 1) * TBK, Kdim, tid);
            asm volatile("cp.async.wait_group %0;\n" :: "n"(1));
        } else {
            asm volatile("cp.async.wait_group %0;\n" :: "n"(0));
        }
        __syncthreads();

        const float* as = As + cur * 128 * ASTR + (size_t)wm * ASTR;
        const float* bs = Bs + cur * 128 * ASTR + (size_t)wn * ASTR;

        #pragma unroll
        for (int ks = 0; ks < 4; ks++) {
            int kb = ks * 8;
            unsigned af[4][4], bf[4][2];
            #pragma unroll
            for (int mi = 0; mi < 4; mi++) {
                const float* p = as + (mi * 16 + lr) * ASTR + kb + lc;
                af[mi][0] = __float_as_uint(p[0]);
                af[mi][1] = __float_as_uint(p[8 * ASTR]);
                af[mi][2] = __float_as_uint(p[4]);
                af[mi][3] = __float_as_uint(p[8 * ASTR + 4]);
            }
            #pragma unroll
            for (int nj = 0; nj < 4; nj++) {
                const float* p = bs + (nj * 8 + lr) * ASTR + kb + lc;
                bf[nj][0] = __float_as_uint(p[0]);
                bf[nj][1] = __float_as_uint(p[4]);
            }
            #pragma unroll
            for (int mi = 0; mi < 4; mi++)
                #pragma unroll
                for (int nj = 0; nj < 4; nj++)
                    asm volatile(
                        "mma.sync.aligned.m16n8k8.row.col.f32.tf32.tf32.f32 "
                        "{%0,%1,%2,%3},{%4,%5,%6,%7},{%8,%9},{%0,%1,%2,%3};\n"
                        : "+f"(acc[mi][nj][0]), "+f"(acc[mi][nj][1]),
                          "+f"(acc[mi][nj][2]), "+f"(acc[mi][nj][3])
                        : "r"(af[mi][0]), "r"(af[mi][1]), "r"(af[mi][2]), "r"(af[mi][3]),
                          "r"(bf[nj][0]), "r"(bf[nj][1]));
        }
        __syncthreads();
    }

    // epilogue
    #pragma unroll
    for (int mi = 0; mi < 4; mi++) {
        int r0 = m0 + wm + mi * 16 + lr;
        #pragma unroll
        for (int nj = 0; nj < 4; nj++) {
            int cc = n0 + wn + nj * 8 + lc * 2;
            float2 v0 = make_float2(acc[mi][nj][0], acc[mi][nj][1]);
            float2 v1 = make_float2(acc[mi][nj][2], acc[mi][nj][3]);
            *(float2*)&C[(size_t)r0 * Ndim + cc]       = v0;
            *(float2*)&C[(size_t)(r0 + 8) * Ndim + cc] = v1;
        }
    }
}

// ---------------- RoPE on q and k (in place) --------------------------------
__global__ void rope_kernel(float* __restrict__ q, float* __restrict__ k,
                            const float* __restrict__ fc, const float* __restrict__ fs)
{
    int idx = blockIdx.x * blockDim.x + threadIdx.x;
    const int PAIRS_PER_ROW = DIMN / 2;
    if (idx >= MTOT * PAIRS_PER_ROW) return;
    int row = idx / PAIRS_PER_ROW;
    int p   = idx % PAIRS_PER_ROW;
    int s   = row & (SEQ - 1);
    int i   = p & (HEAD_DIM / 2 - 1);
    float c  = fc[s * (HEAD_DIM / 2) + i];
    float sn = fs[s * (HEAD_DIM / 2) + i];
    size_t base = (size_t)row * DIMN + p * 2;
    float qr = q[base], qi = q[base + 1];
    q[base]     = qr * c - qi * sn;
    q[base + 1] = qr * sn + qi * c;
    float kr = k[base], ki = k[base + 1];
    k[base]     = kr * c - ki * sn;
    k[base + 1] = kr * sn + ki * c;
}

// ---------------- Flash attention (fp32, online softmax) --------------------
#define BQ  64
#define BKV 64
#define QT_STRIDE 68
#define KT_STRIDE 68
#define VS_STRIDE 132
#define PS_STRIDE 68

#define SMEM_FLOATS (128*QT_STRIDE + 128*KT_STRIDE + BKV*VS_STRIDE + BQ*PS_STRIDE)

__global__ __launch_bounds__(256)
void attn_kernel(const float* __restrict__ Q, const float* __restrict__ K,
                 const float* __restrict__ V, const float* __restrict__ mask,
                 float* __restrict__ O)
{
    extern __shared__ float sm[];
    float* Qt = sm;
    float* Kt = Qt + 128 * QT_STRIDE;
    float* Vs = Kt + 128 * KT_STRIDE;
    float* Ps = Vs + BKV * VS_STRIDE;

    const int tid = threadIdx.x;
    const int tx  = tid & 15;
    const int ty  = tid >> 4;
    const int q0  = blockIdx.x * BQ;
    const int h   = blockIdx.y;
    const int b   = blockIdx.z;
    const float scale = 0.08838834764831845f;

    #pragma unroll
    for (int l = 0; l < 8; l++) {
        int idx = tid + l * 256;
        int r   = idx >> 5;
        int d4  = idx & 31;
        float4 v = *(const float4*)&Q[((size_t)(b * SEQ + q0 + r)) * DIMN + h * HEAD_DIM + d4 * 4];
        Qt[(d4*4+0) * QT_STRIDE + r] = v.x * scale;
        Qt[(d4*4+1) * QT_STRIDE + r] = v.y * scale;
        Qt[(d4*4+2) * QT_STRIDE + r] = v.z * scale;
        Qt[(d4*4+3) * QT_STRIDE + r] = v.w * scale;
    }

    float acc[4][8];
    float m_i[4], l_i[4];
    #pragma unroll
    for (int i = 0; i < 4; i++) {
        m_i[i] = -1e30f; l_i[i] = 0.f;
        #pragma unroll
        for (int j = 0; j < 8; j++) acc[i][j] = 0.f;
    }

    for (int kv0 = 0; kv0 < SEQ; kv0 += BKV) {
        __syncthreads();
        #pragma unroll
        for (int l = 0; l < 8; l++) {
            int idx = tid + l * 256;
            int r   = idx >> 5;
            int d4  = idx & 31;
            size_t goff = ((size_t)(b * SEQ + kv0 + r)) * DIMN + h * HEAD_DIM + d4 * 4;
            float4 kv = *(const float4*)&K[goff];
            Kt[(d4*4+0) * KT_STRIDE + r] = kv.x;
            Kt[(d4*4+1) * KT_STRIDE + r] = kv.y;
            Kt[(d4*4+2) * KT_STRIDE + r] = kv.z;
            Kt[(d4*4+3) * KT_STRIDE + r] = kv.w;
            float4 vv = *(const float4*)&V[goff];
            *(float4*)&Vs[r * VS_STRIDE + d4 * 4] = vv;
        }
        __syncthreads();

        float s[4][4];
        #pragma unroll
        for (int i = 0; i < 4; i++)
            #pragma unroll
            for (int j = 0; j < 4; j++) s[i][j] = 0.f;

        #pragma unroll 4
        for (int kk = 0; kk < HEAD_DIM; kk++) {
            float a[4], bb[4];
            *(float4*)a  = *(const float4*)&Qt[kk * QT_STRIDE + ty * 4];
            *(float4*)bb = *(const float4*)&Kt[kk * KT_STRIDE + tx * 4];
            #pragma unroll
            for (int i = 0; i < 4; i++)
                #pragma unroll
                for (int j = 0; j < 4; j++)
                    s[i][j] += a[i] * bb[j];
        }

        #pragma unroll
        for (int i = 0; i < 4; i++) {
            const float* mrow = &mask[(size_t)(q0 + ty * 4 + i) * SEQ + kv0 + tx * 4];
            #pragma unroll
            for (int j = 0; j < 4; j++) s[i][j] += mrow[j];
        }

        #pragma unroll
        for (int i = 0; i < 4; i++) {
            float mx = fmaxf(fmaxf(s[i][0], s[i][1]), fmaxf(s[i][2], s[i][3]));
            #pragma unroll
            for (int o = 1; o < 16; o <<= 1)
                mx = fmaxf(mx, __shfl_xor_sync(0xffffffffu, mx, o));
            float mnew  = fmaxf(m_i[i], mx);
            float alpha = __expf(m_i[i] - mnew);
            float p[4];
            float rs = 0.f;
            #pragma unroll
            for (int j = 0; j < 4; j++) { p[j] = __expf(s[i][j] - mnew); rs += p[j]; }
            #pragma unroll
            for (int o = 1; o < 16; o <<= 1)
                rs += __shfl_xor_sync(0xffffffffu, rs, o);
            l_i[i] = l_i[i] * alpha + rs;
            m_i[i] = mnew;
            #pragma unroll
            for (int j = 0; j < 8; j++) acc[i][j] *= alpha;
            *(float4*)&Ps[(ty * 4 + i) * PS_STRIDE + tx * 4] = make_float4(p[0], p[1], p[2], p[3]);
        }
        __syncthreads();

        #pragma unroll 8
        for (int kk = 0; kk < BKV; kk++) {
            float pv[4];
            #pragma unroll
            for (int i = 0; i < 4; i++) pv[i] = Ps[(ty * 4 + i) * PS_STRIDE + kk];
            float vr[8];
            *(float4*)&vr[0] = *(const float4*)&Vs[kk * VS_STRIDE + tx * 4];
            *(float4*)&vr[4] = *(const float4*)&Vs[kk * VS_STRIDE + 64 + tx * 4];
            #pragma unroll
            for (int i = 0; i < 4; i++)
                #pragma unroll
                for (int j = 0; j < 8; j++)
                    acc[i][j] += pv[i] * vr[j];
        }
    }

    #pragma unroll
    for (int i = 0; i < 4; i++) {
        float inv = 1.f / l_i[i];
        size_t orow = ((size_t)(b * SEQ + q0 + ty * 4 + i)) * DIMN + h * HEAD_DIM;
        float4 o0 = make_float4(acc[i][0]*inv, acc[i][1]*inv, acc[i][2]*inv, acc[i][3]*inv);
        float4 o1 = make_float4(acc[i][4]*inv, acc[i][5]*inv, acc[i][6]*inv, acc[i][7]*inv);
        *(float4*)&O[orow + tx * 4]      = o0;
        *(float4*)&O[orow + 64 + tx * 4] = o1;
    }
}

// ---------------- launcher ---------------------------------------------------
extern "C" void kernel_launch(void* const* d_in, const int* in_sizes, int n_in,
                              void* d_out, int out_size)
{
    const float* x    = (const float*)d_in[0];
    const float* fcos = (const float*)d_in[1];
    const float* fsin = (const float*)d_in[2];
    const float* mask = (const float*)d_in[3];
    const float* wq   = (const float*)d_in[4];
    const float* wk   = (const float*)d_in[5];
    const float* wv   = (const float*)d_in[6];
    const float* wo   = (const float*)d_in[7];
    float* out = (float*)d_out;

    float *q, *k, *v, *o, *xr, *wqr, *wkr, *wvr, *wor;
    cudaGetSymbolAddress((void**)&q,  g_q);
    cudaGetSymbolAddress((void**)&k,  g_k);
    cudaGetSymbolAddress((void**)&v,  g_v);
    cudaGetSymbolAddress((void**)&o,  g_o);
    cudaGetSymbolAddress((void**)&xr, g_xr);
    cudaGetSymbolAddress((void**)&wqr, g_wq);
    cudaGetSymbolAddress((void**)&wkr, g_wk);
    cudaGetSymbolAddress((void**)&wvr, g_wv);
    cudaGetSymbolAddress((void**)&wor, g_wo);

    const int attn_smem = SMEM_FLOATS * (int)sizeof(float);
    cudaFuncSetAttribute(attn_kernel, cudaFuncAttributeMaxDynamicSharedMemorySize, attn_smem);
    const int gemm_smem = 4 * 128 * ASTR * (int)sizeof(float);   // 73728 B
    cudaFuncSetAttribute(gemm_tf32, cudaFuncAttributeMaxDynamicSharedMemorySize, gemm_smem);

    // 0. tf32-rna pre-rounding of all GEMM operands
    {
        int nx = MTOT * DIMN / 4;     // float4 count
        int nw = DIMN * DIMN / 4;
        round_tf32_kernel<<<(nx + 255) / 256, 256>>>(x,  xr,  nx);
        round_tf32_kernel<<<(nw + 255) / 256, 256>>>(wq, wqr, nw);
        round_tf32_kernel<<<(nw + 255) / 256, 256>>>(wk, wkr, nw);
        round_tf32_kernel<<<(nw + 255) / 256, 256>>>(wv, wvr, nw);
        round_tf32_kernel<<<(nw + 255) / 256, 256>>>(wo, wor, nw);
    }

    dim3 gemm_grid(DIMN / TBN, MTOT / TBM);   // (16, 32)

    // 1. projections (tensor cores)
    gemm_tf32<<<gemm_grid, 256, gemm_smem>>>(xr, wqr, q, MTOT, DIMN, DIMN);
    gemm_tf32<<<gemm_grid, 256, gemm_smem>>>(xr, wkr, k, MTOT, DIMN, DIMN);
    gemm_tf32<<<gemm_grid, 256, gemm_smem>>>(xr, wvr, v, MTOT, DIMN, DIMN);

    // 2. RoPE
    {
        int total = MTOT * (DIMN / 2);
        rope_kernel<<<(total + 255) / 256, 256>>>(q, k, fcos, fsin);
    }

    // 3. attention
    {
        dim3 grid(SEQ / BQ, NHEADS, BATCH);
        attn_kernel<<<grid, 256, attn_smem>>>(q, k, v, mask, o);
    }

    // 4. round attention output, then output projection (tensor cores)
    {
        int no = MTOT * DIMN / 4;
        round_tf32_kernel<<<(no + 255) / 256, 256>>>(o, o, no);
    }
    gemm_tf32<<<gemm_grid, 256, gemm_smem>>>(o, wor, out, MTOT, DIMN, DIMN);
}

// round 3
// speedup vs baseline: 2.7742x; 1.6927x over previous
#include <cuda_runtime.h>
#include <math.h>

#define DIMN     2048
#define NHEADS   16
#define HEAD_DIM 128
#define BATCH    2
#define SEQ      2048
#define MTOT     (BATCH*SEQ)   /* 4096 */

// ---------------- scratch (device globals; no runtime alloc allowed) --------
__device__ float g_q [(size_t)MTOT*DIMN];
__device__ float g_k [(size_t)MTOT*DIMN];
__device__ float g_v [(size_t)MTOT*DIMN];
__device__ float g_o [(size_t)MTOT*DIMN];
__device__ float g_xr[(size_t)MTOT*DIMN];          // tf32-rounded input
__device__ float g_wq[(size_t)DIMN*DIMN];
__device__ float g_wk[(size_t)DIMN*DIMN];
__device__ float g_wv[(size_t)DIMN*DIMN];
__device__ float g_wo[(size_t)DIMN*DIMN];

__device__ __forceinline__ float rna_tf32(float x) {
    unsigned u;
    asm("cvt.rna.tf32.f32 %0, %1;" : "=r"(u) : "f"(x));
    return __uint_as_float(u);
}

#define MMA_TF32(acc, a0,a1,a2,a3, b0,b1)                                    \
    asm volatile(                                                            \
        "mma.sync.aligned.m16n8k8.row.col.f32.tf32.tf32.f32 "                \
        "{%0,%1,%2,%3},{%4,%5,%6,%7},{%8,%9},{%0,%1,%2,%3};\n"               \
        : "+f"(acc[0]), "+f"(acc[1]), "+f"(acc[2]), "+f"(acc[3])             \
        : "r"(a0), "r"(a1), "r"(a2), "r"(a3), "r"(b0), "r"(b1))

// ---------------- tf32 rounding pass (rna, unbiased) -------------------------
__global__ void round_tf32_kernel(const float* __restrict__ in,
                                  float* __restrict__ out, int n4)
{
    int i = blockIdx.x * blockDim.x + threadIdx.x;
    if (i >= n4) return;
    float4 v = ((const float4*)in)[i];
    float4 o;
    o.x = rna_tf32(v.x); o.y = rna_tf32(v.y);
    o.z = rna_tf32(v.z); o.w = rna_tf32(v.w);
    ((float4*)out)[i] = o;
}

// ---------------- tf32 tensor-core GEMM: C[m,n] = sum_k A[m,k]*W[n,k] --------
#define TBM 128
#define TBN 128
#define TBK 32
#define ASTR 36

#define CP_ASYNC16(dst, src) \
    asm volatile("cp.async.cg.shared.global [%0], [%1], 16;\n" :: "r"(dst), "l"(src))

__device__ __forceinline__ void gemm_load_stage(
    float* as, float* bs, const float* __restrict__ A, const float* __restrict__ W,
    int m0, int n0, int k0, int Kdim, int tid)
{
    #pragma unroll
    for (int i = 0; i < 4; i++) {
        int idx = tid + i * 256;
        int row = idx >> 3;
        int c4  = (idx & 7) * 4;
        unsigned da = (unsigned)__cvta_generic_to_shared(as + row * ASTR + c4);
        CP_ASYNC16(da, A + (size_t)(m0 + row) * Kdim + k0 + c4);
        unsigned db = (unsigned)__cvta_generic_to_shared(bs + row * ASTR + c4);
        CP_ASYNC16(db, W + (size_t)(n0 + row) * Kdim + k0 + c4);
    }
    asm volatile("cp.async.commit_group;\n" ::);
}

extern __shared__ float smem_gemm[];

__global__ __launch_bounds__(256, 2)
void gemm_tf32(const float* __restrict__ A, const float* __restrict__ W,
               float* __restrict__ C, int Mdim, int Ndim, int Kdim)
{
    float* As = smem_gemm;
    float* Bs = smem_gemm + 2 * 128 * ASTR;

    const int tid  = threadIdx.x;
    const int wid  = tid >> 5;
    const int lane = tid & 31;
    const int lr   = lane >> 2;
    const int lc   = lane & 3;
    const int wm   = (wid & 1) * 64;
    const int wn   = (wid >> 1) * 32;
    const int m0   = blockIdx.y * TBM;
    const int n0   = blockIdx.x * TBN;

    float acc[4][4][4];
    #pragma unroll
    for (int mi = 0; mi < 4; mi++)
        #pragma unroll
        for (int nj = 0; nj < 4; nj++)
            #pragma unroll
            for (int c = 0; c < 4; c++) acc[mi][nj][c] = 0.f;

    const int NK = Kdim / TBK;

    gemm_load_stage(As, Bs, A, W, m0, n0, 0, Kdim, tid);

    for (int kt = 0; kt < NK; kt++) {
        int cur = kt & 1;
        if (kt + 1 < NK) {
            gemm_load_stage(As + ((kt + 1) & 1) * 128 * ASTR,
                            Bs + ((kt + 1) & 1) * 128 * ASTR,
                            A, W, m0, n0, (kt + 1) * TBK, Kdim, tid);
            asm volatile("cp.async.wait_group %0;\n" :: "n"(1));
        } else {
            asm volatile("cp.async.wait_group %0;\n" :: "n"(0));
        }
        __syncthreads();

        const float* as = As + cur * 128 * ASTR + (size_t)wm * ASTR;
        const float* bs = Bs + cur * 128 * ASTR + (size_t)wn * ASTR;

        #pragma unroll
        for (int ks = 0; ks < 4; ks++) {
            int kb = ks * 8;
            unsigned af[4][4], bf[4][2];
            #pragma unroll
            for (int mi = 0; mi < 4; mi++) {
                const float* p = as + (mi * 16 + lr) * ASTR + kb + lc;
                af[mi][0] = __float_as_uint(p[0]);
                af[mi][1] = __float_as_uint(p[8 * ASTR]);
                af[mi][2] = __float_as_uint(p[4]);
                af[mi][3] = __float_as_uint(p[8 * ASTR + 4]);
            }
            #pragma unroll
            for (int nj = 0; nj < 4; nj++) {
                const float* p = bs + (nj * 8 + lr) * ASTR + kb + lc;
                bf[nj][0] = __float_as_uint(p[0]);
                bf[nj][1] = __float_as_uint(p[4]);
            }
            #pragma unroll
            for (int mi = 0; mi < 4; mi++)
                #pragma unroll
                for (int nj = 0; nj < 4; nj++)
                    MMA_TF32(acc[mi][nj], af[mi][0], af[mi][1], af[mi][2], af[mi][3],
                             bf[nj][0], bf[nj][1]);
        }
        __syncthreads();
    }

    #pragma unroll
    for (int mi = 0; mi < 4; mi++) {
        int r0 = m0 + wm + mi * 16 + lr;
        #pragma unroll
        for (int nj = 0; nj < 4; nj++) {
            int cc = n0 + wn + nj * 8 + lc * 2;
            float2 v0 = make_float2(acc[mi][nj][0], acc[mi][nj][1]);
            float2 v1 = make_float2(acc[mi][nj][2], acc[mi][nj][3]);
            *(float2*)&C[(size_t)r0 * Ndim + cc]       = v0;
            *(float2*)&C[(size_t)(r0 + 8) * Ndim + cc] = v1;
        }
    }
}

// ---------------- RoPE on q and k (in place) --------------------------------
__global__ void rope_kernel(float* __restrict__ q, float* __restrict__ k,
                            const float* __restrict__ fc, const float* __restrict__ fs)
{
    int idx = blockIdx.x * blockDim.x + threadIdx.x;
    const int PAIRS_PER_ROW = DIMN / 2;
    if (idx >= MTOT * PAIRS_PER_ROW) return;
    int row = idx / PAIRS_PER_ROW;
    int p   = idx % PAIRS_PER_ROW;
    int s   = row & (SEQ - 1);
    int i   = p & (HEAD_DIM / 2 - 1);
    float c  = fc[s * (HEAD_DIM / 2) + i];
    float sn = fs[s * (HEAD_DIM / 2) + i];
    size_t base = (size_t)row * DIMN + p * 2;
    float qr = q[base], qi = q[base + 1];
    q[base]     = qr * c - qi * sn;
    q[base + 1] = qr * sn + qi * c;
    float kr = k[base], ki = k[base + 1];
    k[base]     = kr * c - ki * sn;
    k[base + 1] = kr * sn + ki * c;
}

// ---------------- Flash attention on tf32 tensor cores -----------------------
// BQ=128 q rows per block, BKV=64 kv per iter, 8 warps; warp w owns q rows
// [w*16, w*16+16) and full d=128 output in registers.
#define ABQ  128
#define ABKV 64
#define QS   132     /* 132 % 32 == 4 -> conflict-free fragment reads */
#define KS   132
#define VS   132
#define PSRD 68

#define ATTN_SMEM_FLOATS (ABQ*QS + ABKV*KS + ABKV*VS + ABQ*PSRD)

__global__ __launch_bounds__(256)
void attn_tc(const float* __restrict__ Q, const float* __restrict__ K,
             const float* __restrict__ V, const float* __restrict__ mask,
             float* __restrict__ O)
{
    extern __shared__ float sm[];
    float* Qs = sm;                       // [128][132]
    float* Ks = Qs + ABQ * QS;            // [64][132]
    float* Vs = Ks + ABKV * KS;           // [64][132]
    float* Ps = Vs + ABKV * VS;           // [128][68]

    const int tid  = threadIdx.x;
    const int lane = tid & 31;
    const int w    = tid >> 5;
    const int lr   = lane >> 2;           // 0..7
    const int lc   = lane & 3;            // 0..3
    const int q0   = blockIdx.x * ABQ;
    const int h    = blockIdx.y;
    const int b    = blockIdx.z;
    const float scale = 0.08838834764831845f;   // 1/sqrt(128)

    // load Q tile: rounded tf32, pre-scaled
    #pragma unroll
    for (int l = 0; l < 16; l++) {
        int idx = tid + l * 256;          // 0..4095
        int row = idx >> 5;               // 0..127
        int c4  = (idx & 31) * 4;
        float4 v = *(const float4*)&Q[((size_t)(b * SEQ + q0 + row)) * DIMN + h * HEAD_DIM + c4];
        float4 o;
        o.x = rna_tf32(v.x * scale); o.y = rna_tf32(v.y * scale);
        o.z = rna_tf32(v.z * scale); o.w = rna_tf32(v.w * scale);
        *(float4*)&Qs[row * QS + c4] = o;
    }

    float o_acc[16][4];
    #pragma unroll
    for (int nt = 0; nt < 16; nt++)
        #pragma unroll
        for (int c = 0; c < 4; c++) o_acc[nt][c] = 0.f;
    float m_i[2] = {-1e30f, -1e30f};
    float l_i[2] = {0.f, 0.f};

    const int rA = w * 16 + lr;           // q row for c0/c1 (rA+8 for c2/c3)
    const int cb = lc * 2;                // col base within n8 tile

    for (int kv0 = 0; kv0 < SEQ; kv0 += ABKV) {
        __syncthreads();                  // prev iter done with Ks/Vs; Qs ready
        // load K,V tiles (rounded tf32)
        #pragma unroll
        for (int l = 0; l < 8; l++) {
            int idx = tid + l * 256;      // 0..2047
            int row = idx >> 5;           // 0..63
            int c4  = (idx & 31) * 4;
            size_t goff = ((size_t)(b * SEQ + kv0 + row)) * DIMN + h * HEAD_DIM + c4;
            float4 kv = *(const float4*)&K[goff];
            float4 ko;
            ko.x = rna_tf32(kv.x); ko.y = rna_tf32(kv.y);
            ko.z = rna_tf32(kv.z); ko.w = rna_tf32(kv.w);
            *(float4*)&Ks[row * KS + c4] = ko;
            float4 vv = *(const float4*)&V[goff];
            float4 vo;
            vo.x = rna_tf32(vv.x); vo.y = rna_tf32(vv.y);
            vo.z = rna_tf32(vv.z); vo.w = rna_tf32(vv.w);
            *(float4*)&Vs[row * VS + c4] = vo;
        }
        __syncthreads();

        // ---- S = Q K^T : 8 n-tiles of m16n8, k = 128 in 16 k8 steps ----
        float s[8][4];
        #pragma unroll
        for (int nt = 0; nt < 8; nt++)
            #pragma unroll
            for (int c = 0; c < 4; c++) s[nt][c] = 0.f;

        #pragma unroll
        for (int kb = 0; kb < 16; kb++) {
            const float* ap = Qs + rA * QS + kb * 8 + lc;
            unsigned a0 = __float_as_uint(ap[0]);
            unsigned a1 = __float_as_uint(ap[8 * QS]);
            unsigned a2 = __float_as_uint(ap[4]);
            unsigned a3 = __float_as_uint(ap[8 * QS + 4]);
            #pragma unroll
            for (int nt = 0; nt < 8; nt++) {
                const float* bp = Ks + (nt * 8 + lr) * KS + kb * 8 + lc;
                unsigned b0 = __float_as_uint(bp[0]);
                unsigned b1 = __float_as_uint(bp[4]);
                MMA_TF32(s[nt], a0, a1, a2, a3, b0, b1);
            }
        }

        // ---- + mask ----
        #pragma unroll
        for (int nt = 0; nt < 8; nt++) {
            float2 mv0 = *(const float2*)&mask[(size_t)(q0 + rA) * SEQ + kv0 + nt * 8 + cb];
            float2 mv1 = *(const float2*)&mask[(size_t)(q0 + rA + 8) * SEQ + kv0 + nt * 8 + cb];
            s[nt][0] += mv0.x; s[nt][1] += mv0.y;
            s[nt][2] += mv1.x; s[nt][3] += mv1.y;
        }

        // ---- online softmax (rows rA and rA+8) ----
        float mx0 = -1e30f, mx1 = -1e30f;
        #pragma unroll
        for (int nt = 0; nt < 8; nt++) {
            mx0 = fmaxf(mx0, fmaxf(s[nt][0], s[nt][1]));
            mx1 = fmaxf(mx1, fmaxf(s[nt][2], s[nt][3]));
        }
        #pragma unroll
        for (int o = 1; o < 4; o <<= 1) {
            mx0 = fmaxf(mx0, __shfl_xor_sync(0xffffffffu, mx0, o));
            mx1 = fmaxf(mx1, __shfl_xor_sync(0xffffffffu, mx1, o));
        }
        float mn0 = fmaxf(m_i[0], mx0);
        float mn1 = fmaxf(m_i[1], mx1);
        float al0 = __expf(m_i[0] - mn0);
        float al1 = __expf(m_i[1] - mn1);
        float rs0 = 0.f, rs1 = 0.f;
        #pragma unroll
        for (int nt = 0; nt < 8; nt++) {
            float p0 = __expf(s[nt][0] - mn0);
            float p1 = __expf(s[nt][1] - mn0);
            float p2 = __expf(s[nt][2] - mn1);
            float p3 = __expf(s[nt][3] - mn1);
            rs0 += p0 + p1; rs1 += p2 + p3;
            *(float2*)&Ps[rA * PSRD + nt * 8 + cb]       = make_float2(rna_tf32(p0), rna_tf32(p1));
            *(float2*)&Ps[(rA + 8) * PSRD + nt * 8 + cb] = make_float2(rna_tf32(p2), rna_tf32(p3));
        }
        #pragma unroll
        for (int o = 1; o < 4; o <<= 1) {
            rs0 += __shfl_xor_sync(0xffffffffu, rs0, o);
            rs1 += __shfl_xor_sync(0xffffffffu, rs1, o);
        }
        l_i[0] = l_i[0] * al0 + rs0;
        l_i[1] = l_i[1] * al1 + rs1;
        m_i[0] = mn0; m_i[1] = mn1;
        #pragma unroll
        for (int nt = 0; nt < 16; nt++) {
            o_acc[nt][0] *= al0; o_acc[nt][1] *= al0;
            o_acc[nt][2] *= al1; o_acc[nt][3] *= al1;
        }
        __syncthreads();                  // P visible to whole warp's lanes

        // ---- O += P V : 16 n-tiles (d), k = 64 kv in 8 k8 steps ----
        #pragma unroll
        for (int kb = 0; kb < 8; kb++) {
            const float* ap = Ps + rA * PSRD + kb * 8 + lc;
            unsigned a0 = __float_as_uint(ap[0]);
            unsigned a1 = __float_as_uint(ap[8 * PSRD]);
            unsigned a2 = __float_as_uint(ap[4]);
            unsigned a3 = __float_as_uint(ap[8 * PSRD + 4]);
            #pragma unroll
            for (int nt = 0; nt < 16; nt++) {
                const float* bp = Vs + (kb * 8 + lc) * VS + nt * 8 + lr;
                unsigned b0 = __float_as_uint(bp[0]);
                unsigned b1 = __float_as_uint(bp[4 * VS]);
                MMA_TF32(o_acc[nt], a0, a1, a2, a3, b0, b1);
            }
        }
    }

    // ---- normalize + store ----
    float inv0 = 1.f / l_i[0];
    float inv1 = 1.f / l_i[1];
    size_t orow0 = ((size_t)(b * SEQ + q0 + rA)) * DIMN + h * HEAD_DIM;
    size_t orow1 = ((size_t)(b * SEQ + q0 + rA + 8)) * DIMN + h * HEAD_DIM;
    #pragma unroll
    for (int nt = 0; nt < 16; nt++) {
        *(float2*)&O[orow0 + nt * 8 + cb] = make_float2(o_acc[nt][0] * inv0, o_acc[nt][1] * inv0);
        *(float2*)&O[orow1 + nt * 8 + cb] = make_float2(o_acc[nt][2] * inv1, o_acc[nt][3] * inv1);
    }
}

// ---------------- launcher ---------------------------------------------------
extern "C" void kernel_launch(void* const* d_in, const int* in_sizes, int n_in,
                              void* d_out, int out_size)
{
    const float* x    = (const float*)d_in[0];
    const float* fcos = (const float*)d_in[1];
    const float* fsin = (const float*)d_in[2];
    const float* mask = (const float*)d_in[3];
    const float* wq   = (const float*)d_in[4];
    const float* wk   = (const float*)d_in[5];
    const float* wv   = (const float*)d_in[6];
    const float* wo   = (const float*)d_in[7];
    float* out = (float*)d_out;

    float *q, *k, *v, *o, *xr, *wqr, *wkr, *wvr, *wor;
    cudaGetSymbolAddress((void**)&q,  g_q);
    cudaGetSymbolAddress((void**)&k,  g_k);
    cudaGetSymbolAddress((void**)&v,  g_v);
    cudaGetSymbolAddress((void**)&o,  g_o);
    cudaGetSymbolAddress((void**)&xr, g_xr);
    cudaGetSymbolAddress((void**)&wqr, g_wq);
    cudaGetSymbolAddress((void**)&wkr, g_wk);
    cudaGetSymbolAddress((void**)&wvr, g_wv);
    cudaGetSymbolAddress((void**)&wor, g_wo);

    const int gemm_smem = 4 * 128 * ASTR * (int)sizeof(float);
    cudaFuncSetAttribute(gemm_tf32, cudaFuncAttributeMaxDynamicSharedMemorySize, gemm_smem);
    const int attn_smem = ATTN_SMEM_FLOATS * (int)sizeof(float);   // ~166 KB
    cudaFuncSetAttribute(attn_tc, cudaFuncAttributeMaxDynamicSharedMemorySize, attn_smem);

    // 0. tf32-rna pre-rounding of GEMM operands
    {
        int nx = MTOT * DIMN / 4;
        int nw = DIMN * DIMN / 4;
        round_tf32_kernel<<<(nx + 255) / 256, 256>>>(x,  xr,  nx);
        round_tf32_kernel<<<(nw + 255) / 256, 256>>>(wq, wqr, nw);
        round_tf32_kernel<<<(nw + 255) / 256, 256>>>(wk, wkr, nw);
        round_tf32_kernel<<<(nw + 255) / 256, 256>>>(wv, wvr, nw);
        round_tf32_kernel<<<(nw + 255) / 256, 256>>>(wo, wor, nw);
    }

    dim3 gemm_grid(DIMN / TBN, MTOT / TBM);

    // 1. projections (tensor cores)
    gemm_tf32<<<gemm_grid, 256, gemm_smem>>>(xr, wqr, q, MTOT, DIMN, DIMN);
    gemm_tf32<<<gemm_grid, 256, gemm_smem>>>(xr, wkr, k, MTOT, DIMN, DIMN);
    gemm_tf32<<<gemm_grid, 256, gemm_smem>>>(xr, wvr, v, MTOT, DIMN, DIMN);

    // 2. RoPE
    {
        int total = MTOT * (DIMN / 2);
        rope_kernel<<<(total + 255) / 256, 256>>>(q, k, fcos, fsin);
    }

    // 3. attention (tensor cores)
    {
        dim3 grid(SEQ / ABQ, NHEADS, BATCH);   // (16, 16, 2)
        attn_tc<<<grid, 256, attn_smem>>>(q, k, v, mask, o);
    }

    // 4. round attention output, then output projection (tensor cores)
    {
        int no = MTOT * DIMN / 4;
        round_tf32_kernel<<<(no + 255) / 256, 256>>>(o, o, no);
    }
    gemm_tf32<<<gemm_grid, 256, gemm_smem>>>(o, wor, out, MTOT, DIMN, DIMN);
}

// round 5
// speedup vs baseline: 5.5114x; 1.9866x over previous
#include <cuda_runtime.h>
#include <cuda_fp16.h>
#include <math.h>
#include <stdint.h>

#define DIMN     2048
#define NHEADS   16
#define HEAD_DIM 128
#define BATCH    2
#define SEQ      2048
#define MTOT     (BATCH*SEQ)   /* 4096 */

// ---------------- scratch (device globals; no runtime alloc allowed) --------
__device__ __half g_xh [(size_t)MTOT*DIMN];
__device__ __half g_wqh[(size_t)DIMN*DIMN];
__device__ __half g_wkh[(size_t)DIMN*DIMN];
__device__ __half g_wvh[(size_t)DIMN*DIMN];
__device__ __half g_woh[(size_t)DIMN*DIMN];
__device__ float  g_q32[(size_t)MTOT*DIMN];
__device__ float  g_k32[(size_t)MTOT*DIMN];
__device__ float  g_v32[(size_t)MTOT*DIMN];
__device__ __half g_qh [(size_t)MTOT*DIMN];
__device__ __half g_kh [(size_t)MTOT*DIMN];
__device__ __half g_vt [(size_t)MTOT*DIMN];   // [b,h,d,s]
__device__ __half g_oh [(size_t)MTOT*DIMN];

#define CP_ASYNC16(dst, src) \
    asm volatile("cp.async.cg.shared.global [%0], [%1], 16;\n" \
                 :: "r"(dst), "l"(src))
#define CP_COMMIT()  asm volatile("cp.async.commit_group;\n" ::)
#define CP_WAIT(n)   asm volatile("cp.async.wait_group %0;\n" :: "n"(n))

#define MMA_F16(acc, a0,a1,a2,a3, b0,b1)                                     \
    asm volatile(                                                            \
        "mma.sync.aligned.m16n8k16.row.col.f32.f16.f16.f32 "                 \
        "{%0,%1,%2,%3},{%4,%5,%6,%7},{%8,%9},{%0,%1,%2,%3};\n"               \
        : "+f"(acc[0]), "+f"(acc[1]), "+f"(acc[2]), "+f"(acc[3])             \
        : "r"(a0), "r"(a1), "r"(a2), "r"(a3), "r"(b0), "r"(b1))

// ---------------- fp32 -> fp16 rounding pass ---------------------------------
__global__ void round_half(const float* __restrict__ in,
                           __half* __restrict__ out, int n4)
{
    int i = blockIdx.x * blockDim.x + threadIdx.x;
    if (i >= n4) return;
    float4 v = ((const float4*)in)[i];
    half2 h0 = __float22half2_rn(make_float2(v.x, v.y));
    half2 h1 = __float22half2_rn(make_float2(v.z, v.w));
    ((half2*)out)[2 * i]     = h0;
    ((half2*)out)[2 * i + 1] = h1;
}

// ---------------- fp16 tensor-core GEMM: C[m,n] = sum_k A[m,k]*W[n,k] -------
// CTA tile 128x128, BK=32 halfs (64B rows), 8 warps of 64m x 32n.
// z dimension selects one of up to 3 weight/output pairs (QKV fusion).
#define HSTR 40      /* halfs per smem row: 32 + 8 pad; 80B, 16B-aligned, CF */

__global__ __launch_bounds__(256)
void gemm_h(const __half* __restrict__ A,
            const __half* __restrict__ W0, const __half* __restrict__ W1,
            const __half* __restrict__ W2,
            float* __restrict__ C0, float* __restrict__ C1, float* __restrict__ C2)
{
    __shared__ __half As[2][128 * HSTR];
    __shared__ __half Bs[2][128 * HSTR];

    const __half* W = (blockIdx.z == 0) ? W0 : (blockIdx.z == 1 ? W1 : W2);
    float*        C = (blockIdx.z == 0) ? C0 : (blockIdx.z == 1 ? C1 : C2);

    const int tid  = threadIdx.x;
    const int wid  = tid >> 5;
    const int lane = tid & 31;
    const int lr   = lane >> 2;            // 0..7
    const int lc   = lane & 3;             // 0..3
    const int wm   = (wid & 1) * 64;
    const int wn   = (wid >> 1) * 32;
    const int m0   = blockIdx.y * 128;
    const int n0   = blockIdx.x * 128;

    float acc[4][4][4];
    #pragma unroll
    for (int mi = 0; mi < 4; mi++)
        #pragma unroll
        for (int nj = 0; nj < 4; nj++)
            #pragma unroll
            for (int c = 0; c < 4; c++) acc[mi][nj][c] = 0.f;

    // stage loader: 128 rows x 64B each for A and B
    #define G_LOAD(st, k0) do {                                              \
        _Pragma("unroll")                                                    \
        for (int i = 0; i < 2; i++) {                                        \
            int idx = tid + i * 256;                                         \
            int row = idx >> 2;                                              \
            int c16 = idx & 3;                                               \
            unsigned da = (unsigned)__cvta_generic_to_shared(                \
                &As[st][row * HSTR + c16 * 8]);                              \
            CP_ASYNC16(da, (const void*)(A + (size_t)(m0 + row) * DIMN + (k0) + c16 * 8)); \
            unsigned db = (unsigned)__cvta_generic_to_shared(                \
                &Bs[st][row * HSTR + c16 * 8]);                              \
            CP_ASYNC16(db, (const void*)(W + (size_t)(n0 + row) * DIMN + (k0) + c16 * 8)); \
        }                                                                    \
        CP_COMMIT();                                                         \
    } while (0)

    const int NK = DIMN / 32;              // 64
    G_LOAD(0, 0);

    for (int kt = 0; kt < NK; kt++) {
        int cur = kt & 1;
        if (kt + 1 < NK) {
            G_LOAD(cur ^ 1, (kt + 1) * 32);
            CP_WAIT(1);
        } else {
            CP_WAIT(0);
        }
        __syncthreads();

        const __half* as = &As[cur][(size_t)wm * HSTR];
        const __half* bs = &Bs[cur][(size_t)wn * HSTR];

        #pragma unroll
        for (int ks = 0; ks < 2; ks++) {
            int kb = ks * 16;
            unsigned af[4][4], bf[4][2];
            #pragma unroll
            for (int mi = 0; mi < 4; mi++) {
                const __half* p = as + (mi * 16 + lr) * HSTR + kb + lc * 2;
                af[mi][0] = *(const unsigned*)p;
                af[mi][1] = *(const unsigned*)(p + 8 * HSTR);
                af[mi][2] = *(const unsigned*)(p + 8);
                af[mi][3] = *(const unsigned*)(p + 8 * HSTR + 8);
            }
            #pragma unroll
            for (int nj = 0; nj < 4; nj++) {
                const __half* p = bs + (nj * 8 + lr) * HSTR + kb + lc * 2;
                bf[nj][0] = *(const unsigned*)p;
                bf[nj][1] = *(const unsigned*)(p + 8);
            }
            #pragma unroll
            for (int mi = 0; mi < 4; mi++)
                #pragma unroll
                for (int nj = 0; nj < 4; nj++)
                    MMA_F16(acc[mi][nj], af[mi][0], af[mi][1], af[mi][2], af[mi][3],
                            bf[nj][0], bf[nj][1]);
        }
        __syncthreads();
    }

    #pragma unroll
    for (int mi = 0; mi < 4; mi++) {
        int r0 = m0 + wm + mi * 16 + lr;
        #pragma unroll
        for (int nj = 0; nj < 4; nj++) {
            int cc = n0 + wn + nj * 8 + lc * 2;
            *(float2*)&C[(size_t)r0 * DIMN + cc] =
                make_float2(acc[mi][nj][0], acc[mi][nj][1]);
            *(float2*)&C[(size_t)(r0 + 8) * DIMN + cc] =
                make_float2(acc[mi][nj][2], acc[mi][nj][3]);
        }
    }
    #undef G_LOAD
}

// ---------------- RoPE fp32 -> fp16 (scale fused into q) --------------------
__global__ void rope_half(const float* __restrict__ q32, const float* __restrict__ k32,
                          const float* __restrict__ fc, const float* __restrict__ fs,
                          __half* __restrict__ qh, __half* __restrict__ kh)
{
    const float SCALE = 0.08838834764831845f;    // 1/sqrt(128)
    int idx = blockIdx.x * blockDim.x + threadIdx.x;
    const int PAIRS_PER_ROW = DIMN / 2;
    if (idx >= MTOT * PAIRS_PER_ROW) return;
    int row = idx / PAIRS_PER_ROW;
    int p   = idx % PAIRS_PER_ROW;
    int s   = row & (SEQ - 1);
    int i   = p & (HEAD_DIM / 2 - 1);
    float c  = fc[s * (HEAD_DIM / 2) + i];
    float sn = fs[s * (HEAD_DIM / 2) + i];
    size_t base = (size_t)row * DIMN + p * 2;
    float qr = q32[base], qi = q32[base + 1];
    float kr = k32[base], ki = k32[base + 1];
    *(half2*)&qh[base] = __float22half2_rn(
        make_float2((qr * c - qi * sn) * SCALE, (qr * sn + qi * c) * SCALE));
    *(half2*)&kh[base] = __float22half2_rn(
        make_float2(kr * c - ki * sn, kr * sn + ki * c));
}

// ---------------- V transpose: [b,s,h,d] fp32 -> [b,h,d,s] fp16 -------------
__global__ void transpose_v(const float* __restrict__ v32, __half* __restrict__ vt)
{
    __shared__ float t[32][33];
    int s0 = blockIdx.x * 32;
    int d0 = blockIdx.y * 32;
    int bh = blockIdx.z;                 // b*16+h
    int b  = bh >> 4, h = bh & 15;
    int tx = threadIdx.x, ty = threadIdx.y;
    #pragma unroll
    for (int i = 0; i < 4; i++)
        t[ty + i * 8][tx] =
            v32[((size_t)(b * SEQ + s0 + ty + i * 8)) * DIMN + h * HEAD_DIM + d0 + tx];
    __syncthreads();
    #pragma unroll
    for (int i = 0; i < 4; i++)
        vt[((size_t)(bh * HEAD_DIM + d0 + ty + i * 8)) * SEQ + s0 + tx] =
            __float2half_rn(t[tx][ty + i * 8]);
}

// ---------------- Flash attention on fp16 tensor cores ----------------------
// BQ=128 q rows/CTA, BKV=64 per iter (double-buffered cp.async), 8 warps;
// warp w owns q rows [w*16, w*16+16) and full d=128 in registers.
#define AQS 136      /* half stride, 272B rows: conflict-free frag reads */
#define AKS 136
#define AVS 72       /* 144B rows */
#define APS 72

#define ATTN_SMEM_BYTES ((128*AQS + 2*64*AKS + 2*128*AVS + 128*APS) * 2)

__global__ __launch_bounds__(256)
void attn_h(const __half* __restrict__ qh, const __half* __restrict__ kh,
            const __half* __restrict__ vt, const float* __restrict__ mask,
            __half* __restrict__ oh)
{
    extern __shared__ __half smh[];
    __half* Qs = smh;                       // [128][136]
    __half* Ks = Qs + 128 * AQS;            // [2][64][136]
    __half* Vs = Ks + 2 * 64 * AKS;         // [2][128][72]  (d-major)
    __half* Ps = Vs + 2 * 128 * AVS;        // [128][72]

    const int tid  = threadIdx.x;
    const int lane = tid & 31;
    const int w    = tid >> 5;
    const int lr   = lane >> 2;
    const int lc   = lane & 3;
    const int q0   = blockIdx.x * 128;
    const int h    = blockIdx.y;
    const int b    = blockIdx.z;
    const int bh   = b * NHEADS + h;

    // K/V stage loader into stage st for kv offset kv0
    #define KV_LOAD(st, kv0) do {                                            \
        _Pragma("unroll")                                                    \
        for (int l = 0; l < 4; l++) {                                        \
            int idx = tid + l * 256;          /* 0..1023 */                  \
            int rowk = idx >> 4;              /* 0..63  */                   \
            int ck   = idx & 15;                                             \
            unsigned dk = (unsigned)__cvta_generic_to_shared(                \
                Ks + (st) * 64 * AKS + rowk * AKS + ck * 8);                 \
            CP_ASYNC16(dk, (const void*)(kh + ((size_t)(b * SEQ + (kv0) + rowk)) * DIMN \
                                         + h * HEAD_DIM + ck * 8));          \
            int rowv = idx >> 3;              /* 0..127 */                   \
            int cv   = idx & 7;                                              \
            unsigned dv = (unsigned)__cvta_generic_to_shared(                \
                Vs + (st) * 128 * AVS + rowv * AVS + cv * 8);                \
            CP_ASYNC16(dv, (const void*)(vt + ((size_t)(bh * HEAD_DIM + rowv)) * SEQ \
                                         + (kv0) + cv * 8));                 \
        }                                                                    \
        CP_COMMIT();                                                         \
    } while (0)

    // prologue: Q tile + KV stage 0 in one group
    #pragma unroll
    for (int l = 0; l < 8; l++) {
        int idx = tid + l * 256;              // 0..2047
        int row = idx >> 4;                   // 0..127
        int c16 = idx & 15;
        unsigned dq = (unsigned)__cvta_generic_to_shared(Qs + row * AQS + c16 * 8);
        CP_ASYNC16(dq, (const void*)(qh + ((size_t)(b * SEQ + q0 + row)) * DIMN
                                     + h * HEAD_DIM + c16 * 8));
    }
    KV_LOAD(0, 0);

    float o_acc[16][4];
    #pragma unroll
    for (int nt = 0; nt < 16; nt++)
        #pragma unroll
        for (int c = 0; c < 4; c++) o_acc[nt][c] = 0.f;
    float m_i[2] = {-1e30f, -1e30f};
    float l_i[2] = {0.f, 0.f};

    const int rA = w * 16 + lr;
    const int cb = lc * 2;

    const int NIT = SEQ / 64;                 // 32
    for (int it = 0; it < NIT; it++) {
        int st = it & 1;
        int kv0 = it * 64;
        CP_WAIT(0);
        __syncthreads();
        if (it + 1 < NIT) KV_LOAD(st ^ 1, kv0 + 64);

        const __half* ks = Ks + st * 64 * AKS;
        const __half* vs = Vs + st * 128 * AVS;

        // ---- S = Q K^T : 8 n-tiles (kv), 8 k16 steps (d=128) ----
        float s[8][4];
        #pragma unroll
        for (int nt = 0; nt < 8; nt++)
            #pragma unroll
            for (int c = 0; c < 4; c++) s[nt][c] = 0.f;

        #pragma unroll
        for (int kb = 0; kb < 8; kb++) {
            const __half* ap = Qs + rA * AQS + kb * 16 + cb;
            unsigned a0 = *(const unsigned*)ap;
            unsigned a1 = *(const unsigned*)(ap + 8 * AQS);
            unsigned a2 = *(const unsigned*)(ap + 8);
            unsigned a3 = *(const unsigned*)(ap + 8 * AQS + 8);
            #pragma unroll
            for (int nt = 0; nt < 8; nt++) {
                const __half* bp = ks + (nt * 8 + lr) * AKS + kb * 16 + cb;
                unsigned b0 = *(const unsigned*)bp;
                unsigned b1 = *(const unsigned*)(bp + 8);
                MMA_F16(s[nt], a0, a1, a2, a3, b0, b1);
            }
        }

        // ---- + mask ----
        #pragma unroll
        for (int nt = 0; nt < 8; nt++) {
            float2 mv0 = *(const float2*)&mask[(size_t)(q0 + rA) * SEQ + kv0 + nt * 8 + cb];
            float2 mv1 = *(const float2*)&mask[(size_t)(q0 + rA + 8) * SEQ + kv0 + nt * 8 + cb];
            s[nt][0] += mv0.x; s[nt][1] += mv0.y;
            s[nt][2] += mv1.x; s[nt][3] += mv1.y;
        }

        // ---- online softmax ----
        float mx0 = -1e30f, mx1 = -1e30f;
        #pragma unroll
        for (int nt = 0; nt < 8; nt++) {
            mx0 = fmaxf(mx0, fmaxf(s[nt][0], s[nt][1]));
            mx1 = fmaxf(mx1, fmaxf(s[nt][2], s[nt][3]));
        }
        #pragma unroll
        for (int o = 1; o < 4; o <<= 1) {
            mx0 = fmaxf(mx0, __shfl_xor_sync(0xffffffffu, mx0, o));
            mx1 = fmaxf(mx1, __shfl_xor_sync(0xffffffffu, mx1, o));
        }
        float mn0 = fmaxf(m_i[0], mx0);
        float mn1 = fmaxf(m_i[1], mx1);
        float al0 = __expf(m_i[0] - mn0);
        float al1 = __expf(m_i[1] - mn1);
        float rs0 = 0.f, rs1 = 0.f;
        #pragma unroll
        for (int nt = 0; nt < 8; nt++) {
            float p0 = __expf(s[nt][0] - mn0);
            float p1 = __expf(s[nt][1] - mn0);
            float p2 = __expf(s[nt][2] - mn1);
            float p3 = __expf(s[nt][3] - mn1);
            rs0 += p0 + p1; rs1 += p2 + p3;
            *(half2*)&Ps[rA * APS + nt * 8 + cb]       = __float22half2_rn(make_float2(p0, p1));
            *(half2*)&Ps[(rA + 8) * APS + nt * 8 + cb] = __float22half2_rn(make_float2(p2, p3));
        }
        #pragma unroll
        for (int o = 1; o < 4; o <<= 1) {
            rs0 += __shfl_xor_sync(0xffffffffu, rs0, o);
            rs1 += __shfl_xor_sync(0xffffffffu, rs1, o);
        }
        l_i[0] = l_i[0] * al0 + rs0;
        l_i[1] = l_i[1] * al1 + rs1;
        m_i[0] = mn0; m_i[1] = mn1;
        #pragma unroll
        for (int nt = 0; nt < 16; nt++) {
            o_acc[nt][0] *= al0; o_acc[nt][1] *= al0;
            o_acc[nt][2] *= al1; o_acc[nt][3] *= al1;
        }
        __syncthreads();   // Ps visible to all lanes of this warp's tile rows

        // ---- O += P V : 16 n-tiles (d=128), 4 k16 steps (kv=64) ----
        #pragma unroll
        for (int kb = 0; kb < 4; kb++) {
            const __half* ap = Ps + rA * APS + kb * 16 + cb;
            unsigned a0 = *(const unsigned*)ap;
            unsigned a1 = *(const unsigned*)(ap + 8 * APS);
            unsigned a2 = *(const unsigned*)(ap + 8);
            unsigned a3 = *(const unsigned*)(ap + 8 * APS + 8);
            #pragma unroll
            for (int nt = 0; nt < 16; nt++) {
                const __half* bp = vs + (nt * 8 + lr) * AVS + kb * 16 + cb;
                unsigned b0 = *(const unsigned*)bp;
                unsigned b1 = *(const unsigned*)(bp + 8);
                MMA_F16(o_acc[nt], a0, a1, a2, a3, b0, b1);
            }
        }
    }
    #undef KV_LOAD

    // ---- normalize + store fp16 ----
    float inv0 = 1.f / l_i[0];
    float inv1 = 1.f / l_i[1];
    size_t orow0 = ((size_t)(b * SEQ + q0 + rA)) * DIMN + h * HEAD_DIM;
    size_t orow1 = ((size_t)(b * SEQ + q0 + rA + 8)) * DIMN + h * HEAD_DIM;
    #pragma unroll
    for (int nt = 0; nt < 16; nt++) {
        *(half2*)&oh[orow0 + nt * 8 + cb] =
            __float22half2_rn(make_float2(o_acc[nt][0] * inv0, o_acc[nt][1] * inv0));
        *(half2*)&oh[orow1 + nt * 8 + cb] =
            __float22half2_rn(make_float2(o_acc[nt][2] * inv1, o_acc[nt][3] * inv1));
    }
}

// ---------------- launcher ---------------------------------------------------
extern "C" void kernel_launch(void* const* d_in, const int* in_sizes, int n_in,
                              void* d_out, int out_size)
{
    const float* x    = (const float*)d_in[0];
    const float* fcos = (const float*)d_in[1];
    const float* fsin = (const float*)d_in[2];
    const float* mask = (const float*)d_in[3];
    const float* wq   = (const float*)d_in[4];
    const float* wk   = (const float*)d_in[5];
    const float* wv   = (const float*)d_in[6];
    const float* wo   = (const float*)d_in[7];
    float* out = (float*)d_out;

    __half *xh, *wqh, *wkh, *wvh, *woh, *qh, *kh, *vt, *oh;
    float *q32, *k32, *v32;
    cudaGetSymbolAddress((void**)&xh,  g_xh);
    cudaGetSymbolAddress((void**)&wqh, g_wqh);
    cudaGetSymbolAddress((void**)&wkh, g_wkh);
    cudaGetSymbolAddress((void**)&wvh, g_wvh);
    cudaGetSymbolAddress((void**)&woh, g_woh);
    cudaGetSymbolAddress((void**)&q32, g_q32);
    cudaGetSymbolAddress((void**)&k32, g_k32);
    cudaGetSymbolAddress((void**)&v32, g_v32);
    cudaGetSymbolAddress((void**)&qh,  g_qh);
    cudaGetSymbolAddress((void**)&kh,  g_kh);
    cudaGetSymbolAddress((void**)&vt,  g_vt);
    cudaGetSymbolAddress((void**)&oh,  g_oh);

    cudaFuncSetAttribute(attn_h, cudaFuncAttributeMaxDynamicSharedMemorySize,
                         ATTN_SMEM_BYTES);

    // 0. rn-round x + weights to fp16
    {
        int nx = MTOT * DIMN / 4;
        int nw = DIMN * DIMN / 4;
        round_half<<<(nx + 255) / 256, 256>>>(x,  xh,  nx);
        round_half<<<(nw + 255) / 256, 256>>>(wq, wqh, nw);
        round_half<<<(nw + 255) / 256, 256>>>(wk, wkh, nw);
        round_half<<<(nw + 255) / 256, 256>>>(wv, wvh, nw);
        round_half<<<(nw + 255) / 256, 256>>>(wo, woh, nw);
    }

    // 1. fused QKV projections (fp16 mma)
    {
        dim3 grid(DIMN / 128, MTOT / 128, 3);   // (16, 32, 3)
        gemm_h<<<grid, 256>>>(xh, wqh, wkh, wvh, q32, k32, v32);
    }

    // 2. RoPE (fp32 math, single fp16 rounding, q pre-scaled)
    {
        int total = MTOT * (DIMN / 2);
        rope_half<<<(total + 255) / 256, 256>>>(q32, k32, fcos, fsin, qh, kh);
    }

    // 3. V transpose to [b,h,d,s] fp16
    {
        dim3 grid(SEQ / 32, HEAD_DIM / 32, BATCH * NHEADS);
        transpose_v<<<grid, dim3(32, 8)>>>(v32, vt);
    }

    // 4. attention (fp16 mma, cp.async double-buffered K/V)
    {
        dim3 grid(SEQ / 128, NHEADS, BATCH);    // (16, 16, 2)
        attn_h<<<grid, 256, ATTN_SMEM_BYTES>>>(qh, kh, vt, mask, oh);
    }

    // 5. output projection -> d_out (fp32)
    {
        dim3 grid(DIMN / 128, MTOT / 128, 1);
        gemm_h<<<grid, 256>>>(oh, woh, woh, woh, out, out, out);
    }
}

// round 6
// speedup vs baseline: 6.4538x; 1.1710x over previous
#include <cuda_runtime.h>
#include <cuda_fp16.h>
#include <math.h>
#include <stdint.h>

#define DIMN     2048
#define NHEADS   16
#define HEAD_DIM 128
#define BATCH    2
#define SEQ      2048
#define MTOT     (BATCH*SEQ)   /* 4096 */

// ---------------- scratch (device globals; no runtime alloc allowed) --------
__device__ __half g_xh [(size_t)MTOT*DIMN];
__device__ __half g_wqh[(size_t)DIMN*DIMN];
__device__ __half g_wkh[(size_t)DIMN*DIMN];
__device__ __half g_wvh[(size_t)DIMN*DIMN];
__device__ __half g_woh[(size_t)DIMN*DIMN];
__device__ __half g_qh [(size_t)MTOT*DIMN];
__device__ __half g_kh [(size_t)MTOT*DIMN];
__device__ __half g_vt [(size_t)MTOT*DIMN];   // [b,h,d,s]
__device__ __half g_oh [(size_t)MTOT*DIMN];

#define CP_ASYNC16(dst, src) \
    asm volatile("cp.async.cg.shared.global [%0], [%1], 16;\n" \
                 :: "r"(dst), "l"(src))
#define CP_COMMIT()  asm volatile("cp.async.commit_group;\n" ::)
#define CP_WAIT(n)   asm volatile("cp.async.wait_group %0;\n" :: "n"(n))

#define MMA_F16(acc, a0,a1,a2,a3, b0,b1)                                     \
    asm volatile(                                                            \
        "mma.sync.aligned.m16n8k16.row.col.f32.f16.f16.f32 "                 \
        "{%0,%1,%2,%3},{%4,%5,%6,%7},{%8,%9},{%0,%1,%2,%3};\n"               \
        : "+f"(acc[0]), "+f"(acc[1]), "+f"(acc[2]), "+f"(acc[3])             \
        : "r"(a0), "r"(a1), "r"(a2), "r"(a3), "r"(b0), "r"(b1))

#define LDSM_X4(r0, r1, r2, r3, gp)                                          \
    asm volatile("ldmatrix.sync.aligned.m8n8.x4.shared.b16 {%0,%1,%2,%3}, [%4];" \
        : "=r"(r0), "=r"(r1), "=r"(r2), "=r"(r3)                             \
        : "r"((unsigned)__cvta_generic_to_shared(gp)))

__device__ __forceinline__ unsigned pack_half2_rn(float a, float b) {
    half2 h = __float22half2_rn(make_float2(a, b));
    return *(unsigned*)&h;
}

// ---------------- fp32 -> fp16 rounding pass ---------------------------------
__global__ void round_half(const float* __restrict__ in,
                           __half* __restrict__ out, int n4)
{
    int i = blockIdx.x * blockDim.x + threadIdx.x;
    if (i >= n4) return;
    float4 v = ((const float4*)in)[i];
    ((half2*)out)[2 * i]     = __float22half2_rn(make_float2(v.x, v.y));
    ((half2*)out)[2 * i + 1] = __float22half2_rn(make_float2(v.z, v.w));
}

// ---------------- shared fp16 GEMM mainloop ----------------------------------
// C[m,n] = sum_k A[m,k] * W[n,k]; CTA tile 128x128, BK=32 halfs; 8 warps 64x32.
#define HSTR 40      /* halfs per smem row: 32 + 8 pad (80B) */

__device__ __forceinline__ void gemm_mainloop(
    const __half* __restrict__ A, const __half* __restrict__ W,
    __half* As, __half* Bs, int m0, int n0, float acc[4][4][4])
{
    const int tid  = threadIdx.x;
    const int wid  = tid >> 5;
    const int lane = tid & 31;
    const int wm   = (wid & 1) * 64;
    const int wn   = (wid >> 1) * 32;

    // ldmatrix lane offsets
    const int a_off = (lane & 15) * HSTR + (lane >> 4) * 8;
    const int b_off = ((lane & 7) + (lane >> 4) * 8) * HSTR + ((lane >> 3) & 1) * 8;

    #define G_LOAD(st, k0) do {                                              \
        _Pragma("unroll")                                                    \
        for (int i = 0; i < 2; i++) {                                        \
            int idx = tid + i * 256;                                         \
            int row = idx >> 2;                                              \
            int c16 = idx & 3;                                               \
            unsigned da = (unsigned)__cvta_generic_to_shared(                \
                As + (st) * 128 * HSTR + row * HSTR + c16 * 8);              \
            CP_ASYNC16(da, (const void*)(A + (size_t)(m0 + row) * DIMN + (k0) + c16 * 8)); \
            unsigned db = (unsigned)__cvta_generic_to_shared(                \
                Bs + (st) * 128 * HSTR + row * HSTR + c16 * 8);              \
            CP_ASYNC16(db, (const void*)(W + (size_t)(n0 + row) * DIMN + (k0) + c16 * 8)); \
        }                                                                    \
        CP_COMMIT();                                                         \
    } while (0)

    const int NK = DIMN / 32;              // 64
    G_LOAD(0, 0);

    for (int kt = 0; kt < NK; kt++) {
        int cur = kt & 1;
        if (kt + 1 < NK) {
            G_LOAD(cur ^ 1, (kt + 1) * 32);
            CP_WAIT(1);
        } else {
            CP_WAIT(0);
        }
        __syncthreads();

        const __half* as = As + cur * 128 * HSTR + (size_t)wm * HSTR;
        const __half* bs = Bs + cur * 128 * HSTR + (size_t)wn * HSTR;

        #pragma unroll
        for (int ks = 0; ks < 2; ks++) {
            int kb = ks * 16;
            unsigned af[4][4], bf[4][2];
            #pragma unroll
            for (int mi = 0; mi < 4; mi++)
                LDSM_X4(af[mi][0], af[mi][1], af[mi][2], af[mi][3],
                        as + mi * 16 * HSTR + kb + a_off);
            #pragma unroll
            for (int njp = 0; njp < 2; njp++)
                LDSM_X4(bf[2*njp][0], bf[2*njp][1], bf[2*njp+1][0], bf[2*njp+1][1],
                        bs + njp * 16 * HSTR + kb + b_off);
            #pragma unroll
            for (int mi = 0; mi < 4; mi++)
                #pragma unroll
                for (int nj = 0; nj < 4; nj++)
                    MMA_F16(acc[mi][nj], af[mi][0], af[mi][1], af[mi][2], af[mi][3],
                            bf[nj][0], bf[nj][1]);
        }
        __syncthreads();
    }
    #undef G_LOAD
}

// ---------------- QKV GEMM with fused RoPE / V-transpose epilogue -----------
__global__ __launch_bounds__(256)
void gemm_qkv(const __half* __restrict__ xh,
              const __half* __restrict__ wqh, const __half* __restrict__ wkh,
              const __half* __restrict__ wvh,
              const float* __restrict__ fc, const float* __restrict__ fs,
              __half* __restrict__ qh, __half* __restrict__ kh,
              __half* __restrict__ vt)
{
    __shared__ __half As[2 * 128 * HSTR];
    __shared__ __half Bs[2 * 128 * HSTR];

    const int z = blockIdx.z;
    const __half* W = (z == 0) ? wqh : (z == 1 ? wkh : wvh);
    const int m0 = blockIdx.y * 128;
    const int n0 = blockIdx.x * 128;

    float acc[4][4][4];
    #pragma unroll
    for (int mi = 0; mi < 4; mi++)
        #pragma unroll
        for (int nj = 0; nj < 4; nj++)
            #pragma unroll
            for (int c = 0; c < 4; c++) acc[mi][nj][c] = 0.f;

    gemm_mainloop(xh, W, As, Bs, m0, n0, acc);

    const int tid  = threadIdx.x;
    const int wid  = tid >> 5;
    const int lane = tid & 31;
    const int lr   = lane >> 2;
    const int lc   = lane & 3;
    const int wm   = (wid & 1) * 64;
    const int wn   = (wid >> 1) * 32;
    const float SCALE = 0.08838834764831845f;   // 1/sqrt(128)

    if (z == 2) {
        // V: write transposed fp16 [b,h,d,s]
        #pragma unroll
        for (int mi = 0; mi < 4; mi++) {
            int r0 = m0 + wm + mi * 16 + lr;
            int b  = r0 >> 11;
            int s  = r0 & (SEQ - 1);
            #pragma unroll
            for (int nj = 0; nj < 4; nj++) {
                int cc = n0 + wn + nj * 8 + lc * 2;
                int h  = cc >> 7, d = cc & 127;
                size_t base = ((size_t)((b * NHEADS + h) * HEAD_DIM + d)) * SEQ;
                vt[base + s]           = __float2half_rn(acc[mi][nj][0]);
                vt[base + SEQ + s]     = __float2half_rn(acc[mi][nj][1]);
                vt[base + s + 8]       = __float2half_rn(acc[mi][nj][2]);
                vt[base + SEQ + s + 8] = __float2half_rn(acc[mi][nj][3]);
            }
        }
    } else {
        __half* dst = (z == 0) ? qh : kh;
        float sc = (z == 0) ? SCALE : 1.f;
        #pragma unroll
        for (int mi = 0; mi < 4; mi++) {
            int r0 = m0 + wm + mi * 16 + lr;
            int s1 = r0 & (SEQ - 1);          // rows r0, r0+8 in same batch
            #pragma unroll
            for (int nj = 0; nj < 4; nj++) {
                int cc = n0 + wn + nj * 8 + lc * 2;
                int fi = (cc & 127) >> 1;
                float c1 = fc[s1 * 64 + fi],       n1 = fs[s1 * 64 + fi];
                float c2 = fc[(s1 + 8) * 64 + fi], n2 = fs[(s1 + 8) * 64 + fi];
                float e1 = acc[mi][nj][0], o1 = acc[mi][nj][1];
                float e2 = acc[mi][nj][2], o2 = acc[mi][nj][3];
                *(half2*)&dst[(size_t)r0 * DIMN + cc] = __float22half2_rn(
                    make_float2((e1 * c1 - o1 * n1) * sc, (e1 * n1 + o1 * c1) * sc));
                *(half2*)&dst[(size_t)(r0 + 8) * DIMN + cc] = __float22half2_rn(
                    make_float2((e2 * c2 - o2 * n2) * sc, (e2 * n2 + o2 * c2) * sc));
            }
        }
    }
}

// ---------------- output projection GEMM (fp32 epilogue) --------------------
__global__ __launch_bounds__(256)
void gemm_out(const __half* __restrict__ A, const __half* __restrict__ W,
              float* __restrict__ C)
{
    __shared__ __half As[2 * 128 * HSTR];
    __shared__ __half Bs[2 * 128 * HSTR];

    const int m0 = blockIdx.y * 128;
    const int n0 = blockIdx.x * 128;

    float acc[4][4][4];
    #pragma unroll
    for (int mi = 0; mi < 4; mi++)
        #pragma unroll
        for (int nj = 0; nj < 4; nj++)
            #pragma unroll
            for (int c = 0; c < 4; c++) acc[mi][nj][c] = 0.f;

    gemm_mainloop(A, W, As, Bs, m0, n0, acc);

    const int tid  = threadIdx.x;
    const int wid  = tid >> 5;
    const int lane = tid & 31;
    const int lr   = lane >> 2;
    const int lc   = lane & 3;
    const int wm   = (wid & 1) * 64;
    const int wn   = (wid >> 1) * 32;

    #pragma unroll
    for (int mi = 0; mi < 4; mi++) {
        int r0 = m0 + wm + mi * 16 + lr;
        #pragma unroll
        for (int nj = 0; nj < 4; nj++) {
            int cc = n0 + wn + nj * 8 + lc * 2;
            *(float2*)&C[(size_t)r0 * DIMN + cc] =
                make_float2(acc[mi][nj][0], acc[mi][nj][1]);
            *(float2*)&C[(size_t)(r0 + 8) * DIMN + cc] =
                make_float2(acc[mi][nj][2], acc[mi][nj][3]);
        }
    }
}

// ---------------- Flash attention, fp16 mma, register-P, ldmatrix -----------
#define AQS 136      /* half stride: 272B rows */
#define AKS 136
#define AVS 72       /* 144B rows */

#define ATTN_SMEM_BYTES ((128*AQS + 2*64*AKS + 2*128*AVS) * 2)

__global__ __launch_bounds__(256)
void attn_h(const __half* __restrict__ qh, const __half* __restrict__ kh,
            const __half* __restrict__ vt, const float* __restrict__ mask,
            __half* __restrict__ oh)
{
    extern __shared__ __half smh[];
    __half* Qs = smh;                       // [128][136]
    __half* Ks = Qs + 128 * AQS;            // [2][64][136]
    __half* Vs = Ks + 2 * 64 * AKS;         // [2][128][72]  (d-major)

    const int tid  = threadIdx.x;
    const int lane = tid & 31;
    const int w    = tid >> 5;
    const int lr   = lane >> 2;
    const int lc   = lane & 3;
    const int q0   = blockIdx.x * 128;
    const int h    = blockIdx.y;
    const int b    = blockIdx.z;
    const int bh   = b * NHEADS + h;

    // ldmatrix lane offsets
    const int aq_off = (lane & 15) * AQS + (lane >> 4) * 8;
    const int bk_off = ((lane & 7) + (lane >> 4) * 8) * AKS + ((lane >> 3) & 1) * 8;
    const int bv_off = ((lane & 7) + (lane >> 4) * 8) * AVS + ((lane >> 3) & 1) * 8;

    #define KV_LOAD(st, kv0) do {                                            \
        _Pragma("unroll")                                                    \
        for (int l = 0; l < 4; l++) {                                        \
            int idx = tid + l * 256;          /* 0..1023 */                  \
            int rowk = idx >> 4;              /* 0..63  */                   \
            int ck   = idx & 15;                                             \
            unsigned dk = (unsigned)__cvta_generic_to_shared(                \
                Ks + (st) * 64 * AKS + rowk * AKS + ck * 8);                 \
            CP_ASYNC16(dk, (const void*)(kh + ((size_t)(b * SEQ + (kv0) + rowk)) * DIMN \
                                         + h * HEAD_DIM + ck * 8));          \
            int rowv = idx >> 3;              /* 0..127 */                   \
            int cv   = idx & 7;                                              \
            unsigned dv = (unsigned)__cvta_generic_to_shared(                \
                Vs + (st) * 128 * AVS + rowv * AVS + cv * 8);                \
            CP_ASYNC16(dv, (const void*)(vt + ((size_t)(bh * HEAD_DIM + rowv)) * SEQ \
                                         + (kv0) + cv * 8));                 \
        }                                                                    \
        CP_COMMIT();                                                         \
    } while (0)

    // prologue: Q tile + KV stage 0 in one group
    #pragma unroll
    for (int l = 0; l < 8; l++) {
        int idx = tid + l * 256;              // 0..2047
        int row = idx >> 4;                   // 0..127
        int c16 = idx & 15;
        unsigned dq = (unsigned)__cvta_generic_to_shared(Qs + row * AQS + c16 * 8);
        CP_ASYNC16(dq, (const void*)(qh + ((size_t)(b * SEQ + q0 + row)) * DIMN
                                     + h * HEAD_DIM + c16 * 8));
    }
    KV_LOAD(0, 0);

    CP_WAIT(0);
    __syncthreads();

    // hoist Q fragments for the whole kv loop (8 k16 blocks)
    unsigned aq[8][4];
    #pragma unroll
    for (int kb = 0; kb < 8; kb++)
        LDSM_X4(aq[kb][0], aq[kb][1], aq[kb][2], aq[kb][3],
                Qs + w * 16 * AQS + kb * 16 + aq_off);

    float o_acc[16][4];
    #pragma unroll
    for (int nt = 0; nt < 16; nt++)
        #pragma unroll
        for (int c = 0; c < 4; c++) o_acc[nt][c] = 0.f;
    float m_i[2] = {-1e30f, -1e30f};
    float l_i[2] = {0.f, 0.f};

    const int rA = w * 16 + lr;
    const int cb = lc * 2;

    const int NIT = SEQ / 64;                 // 32
    for (int it = 0; it < NIT; it++) {
        int st = it & 1;
        int kv0 = it * 64;
        if (it + 1 < NIT) KV_LOAD(st ^ 1, kv0 + 64);

        const __half* ks = Ks + st * 64 * AKS;
        const __half* vs = Vs + st * 128 * AVS;

        // ---- S = Q K^T : 8 n-tiles (kv), 8 k16 steps (d=128) ----
        float s[8][4];
        #pragma unroll
        for (int nt = 0; nt < 8; nt++)
            #pragma unroll
            for (int c = 0; c < 4; c++) s[nt][c] = 0.f;

        #pragma unroll
        for (int kb = 0; kb < 8; kb++) {
            #pragma unroll
            for (int ntp = 0; ntp < 4; ntp++) {
                unsigned b0, b1, b2, b3;
                LDSM_X4(b0, b1, b2, b3, ks + ntp * 16 * AKS + kb * 16 + bk_off);
                MMA_F16(s[2*ntp],   aq[kb][0], aq[kb][1], aq[kb][2], aq[kb][3], b0, b1);
                MMA_F16(s[2*ntp+1], aq[kb][0], aq[kb][1], aq[kb][2], aq[kb][3], b2, b3);
            }
        }

        // ---- + mask ----
        #pragma unroll
        for (int nt = 0; nt < 8; nt++) {
            float2 mv0 = *(const float2*)&mask[(size_t)(q0 + rA) * SEQ + kv0 + nt * 8 + cb];
            float2 mv1 = *(const float2*)&mask[(size_t)(q0 + rA + 8) * SEQ + kv0 + nt * 8 + cb];
            s[nt][0] += mv0.x; s[nt][1] += mv0.y;
            s[nt][2] += mv1.x; s[nt][3] += mv1.y;
        }

        // ---- online softmax (rows rA, rA+8) ----
        float mx0 = -1e30f, mx1 = -1e30f;
        #pragma unroll
        for (int nt = 0; nt < 8; nt++) {
            mx0 = fmaxf(mx0, fmaxf(s[nt][0], s[nt][1]));
            mx1 = fmaxf(mx1, fmaxf(s[nt][2], s[nt][3]));
        }
        #pragma unroll
        for (int o = 1; o < 4; o <<= 1) {
            mx0 = fmaxf(mx0, __shfl_xor_sync(0xffffffffu, mx0, o));
            mx1 = fmaxf(mx1, __shfl_xor_sync(0xffffffffu, mx1, o));
        }
        float mn0 = fmaxf(m_i[0], mx0);
        float mn1 = fmaxf(m_i[1], mx1);
        float al0 = __expf(m_i[0] - mn0);
        float al1 = __expf(m_i[1] - mn1);
        float rs0 = 0.f, rs1 = 0.f;
        #pragma unroll
        for (int nt = 0; nt < 8; nt++) {
            s[nt][0] = __expf(s[nt][0] - mn0);
            s[nt][1] = __expf(s[nt][1] - mn0);
            s[nt][2] = __expf(s[nt][2] - mn1);
            s[nt][3] = __expf(s[nt][3] - mn1);
            rs0 += s[nt][0] + s[nt][1];
            rs1 += s[nt][2] + s[nt][3];
        }
        #pragma unroll
        for (int o = 1; o < 4; o <<= 1) {
            rs0 += __shfl_xor_sync(0xffffffffu, rs0, o);
            rs1 += __shfl_xor_sync(0xffffffffu, rs1, o);
        }
        l_i[0] = l_i[0] * al0 + rs0;
        l_i[1] = l_i[1] * al1 + rs1;
        m_i[0] = mn0; m_i[1] = mn1;
        #pragma unroll
        for (int nt = 0; nt < 16; nt++) {
            o_acc[nt][0] *= al0; o_acc[nt][1] *= al0;
            o_acc[nt][2] *= al1; o_acc[nt][3] *= al1;
        }

        // ---- P -> A fragments in registers (S-fragment == A-fragment) ----
        unsigned pa[4][4];
        #pragma unroll
        for (int kb = 0; kb < 4; kb++) {
            pa[kb][0] = pack_half2_rn(s[2*kb][0],   s[2*kb][1]);
            pa[kb][1] = pack_half2_rn(s[2*kb][2],   s[2*kb][3]);
            pa[kb][2] = pack_half2_rn(s[2*kb+1][0], s[2*kb+1][1]);
            pa[kb][3] = pack_half2_rn(s[2*kb+1][2], s[2*kb+1][3]);
        }

        // ---- O += P V : 16 n-tiles (d=128), 4 k16 steps (kv=64) ----
        #pragma unroll
        for (int kb = 0; kb < 4; kb++) {
            #pragma unroll
            for (int ntp = 0; ntp < 8; ntp++) {
                unsigned b0, b1, b2, b3;
                LDSM_X4(b0, b1, b2, b3, vs + ntp * 16 * AVS + kb * 16 + bv_off);
                MMA_F16(o_acc[2*ntp],   pa[kb][0], pa[kb][1], pa[kb][2], pa[kb][3], b0, b1);
                MMA_F16(o_acc[2*ntp+1], pa[kb][0], pa[kb][1], pa[kb][2], pa[kb][3], b2, b3);
            }
        }

        if (it + 1 < NIT) {
            CP_WAIT(0);
            __syncthreads();
        }
    }
    #undef KV_LOAD

    // ---- normalize + store fp16 ----
    float inv0 = 1.f / l_i[0];
    float inv1 = 1.f / l_i[1];
    size_t orow0 = ((size_t)(b * SEQ + q0 + rA)) * DIMN + h * HEAD_DIM;
    size_t orow1 = ((size_t)(b * SEQ + q0 + rA + 8)) * DIMN + h * HEAD_DIM;
    #pragma unroll
    for (int nt = 0; nt < 16; nt++) {
        *(half2*)&oh[orow0 + nt * 8 + cb] =
            __float22half2_rn(make_float2(o_acc[nt][0] * inv0, o_acc[nt][1] * inv0));
        *(half2*)&oh[orow1 + nt * 8 + cb] =
            __float22half2_rn(make_float2(o_acc[nt][2] * inv1, o_acc[nt][3] * inv1));
    }
}

// ---------------- launcher ---------------------------------------------------
extern "C" void kernel_launch(void* const* d_in, const int* in_sizes, int n_in,
                              void* d_out, int out_size)
{
    const float* x    = (const float*)d_in[0];
    const float* fcos = (const float*)d_in[1];
    const float* fsin = (const float*)d_in[2];
    const float* mask = (const float*)d_in[3];
    const float* wq   = (const float*)d_in[4];
    const float* wk   = (const float*)d_in[5];
    const float* wv   = (const float*)d_in[6];
    const float* wo   = (const float*)d_in[7];
    float* out = (float*)d_out;

    __half *xh, *wqh, *wkh, *wvh, *woh, *qh, *kh, *vt, *oh;
    cudaGetSymbolAddress((void**)&xh,  g_xh);
    cudaGetSymbolAddress((void**)&wqh, g_wqh);
    cudaGetSymbolAddress((void**)&wkh, g_wkh);
    cudaGetSymbolAddress((void**)&wvh, g_wvh);
    cudaGetSymbolAddress((void**)&woh, g_woh);
    cudaGetSymbolAddress((void**)&qh,  g_qh);
    cudaGetSymbolAddress((void**)&kh,  g_kh);
    cudaGetSymbolAddress((void**)&vt,  g_vt);
    cudaGetSymbolAddress((void**)&oh,  g_oh);

    cudaFuncSetAttribute(attn_h, cudaFuncAttributeMaxDynamicSharedMemorySize,
                         ATTN_SMEM_BYTES);

    // 0. rn-round x + weights to fp16
    {
        int nx = MTOT * DIMN / 4;
        int nw = DIMN * DIMN / 4;
        round_half<<<(nx + 255) / 256, 256>>>(x,  xh,  nx);
        round_half<<<(nw + 255) / 256, 256>>>(wq, wqh, nw);
        round_half<<<(nw + 255) / 256, 256>>>(wk, wkh, nw);
        round_half<<<(nw + 255) / 256, 256>>>(wv, wvh, nw);
        round_half<<<(nw + 255) / 256, 256>>>(wo, woh, nw);
    }

    // 1. fused QKV projections + RoPE + V transpose
    {
        dim3 grid(DIMN / 128, MTOT / 128, 3);   // (16, 32, 3)
        gemm_qkv<<<grid, 256>>>(xh, wqh, wkh, wvh, fcos, fsin, qh, kh, vt);
    }

    // 2. attention
    {
        dim3 grid(SEQ / 128, NHEADS, BATCH);    // (16, 16, 2)
        attn_h<<<grid, 256, ATTN_SMEM_BYTES>>>(qh, kh, vt, mask, oh);
    }

    // 3. output projection -> d_out (fp32)
    {
        dim3 grid(DIMN / 128, MTOT / 128, 1);
        gemm_out<<<grid, 256>>>(oh, woh, out);
    }
}